// round 1
// baseline (speedup 1.0000x reference)
#include <cuda_runtime.h>
#include <math.h>

// Problem constants
#define BATCH 8
#define CCH   256        // channels C
#define HW    16384      // H*W = 128*128
#define HID   512        // hidden = 2*C
#define CHUNK 64
#define NG    (HW / CHUNK)   // 256 chunks per image

// ---------------- scratch (module-load allocated, allowed) ----------------
__device__ float g_xln [BATCH * CCH * HW];       // LN1 out, reused for LN2 out (NCHW)
__device__ float g_qkv [BATCH * 3 * CCH * HW];   // (b, m=0..767, p)
__device__ float g_attn[BATCH * CCH * HW];       // attention output (NCHW)
__device__ float g_x2  [BATCH * CCH * HW];       // x + attn (NCHW)
__device__ float g_h1  [BATCH * HID * HW];       // conv1+gelu out
__device__ float g_h2  [BATCH * HID * HW];       // dwconv+gelu out

__device__ __forceinline__ float gelu_f(float v) {
    return 0.5f * v * (1.0f + erff(v * 0.70710678118654752f));
}

// ---------------- LayerNorm over channels at each (b, p) ----------------
__global__ void ln_kernel(const float* __restrict__ in,
                          const float* __restrict__ scale,
                          const float* __restrict__ bias,
                          float* __restrict__ out)
{
    int gid = blockIdx.x * blockDim.x + threadIdx.x;   // over BATCH*HW
    int b = gid >> 14;
    int p = gid & (HW - 1);
    const float* ip = in  + (size_t)b * CCH * HW + p;
    float*       op = out + (size_t)b * CCH * HW + p;

    float s = 0.f, s2 = 0.f;
#pragma unroll 8
    for (int c = 0; c < CCH; c++) {
        float v = ip[(size_t)c * HW];
        s += v; s2 += v * v;
    }
    float mu  = s  * (1.0f / CCH);
    float var = s2 * (1.0f / CCH) - mu * mu;
    float r   = rsqrtf(var + 1e-5f);
#pragma unroll 8
    for (int c = 0; c < CCH; c++) {
        float v = ip[(size_t)c * HW];
        op[(size_t)c * HW] = (v - mu) * r * scale[c] + bias[c];
    }
}

// ---------------- SGEMM: C[b][m][p] = sum_k A[m][k] * B[b][k][p] (+epilogue) ----
// A row-major (M x K). B per-batch (K x HW). 128x128 tile, BK=8, 256 thr, 8x8 reg tile.
// epi: 0 = +bias ; 1 = +bias + Res ; 2 = gelu(+bias)
__global__ __launch_bounds__(256, 2)
void sgemm_kernel(const float* __restrict__ A, const float* __restrict__ Bm,
                  const float* __restrict__ bias, const float* __restrict__ Res,
                  float* __restrict__ C, int K,
                  long strideB, long strideC, int epi)
{
    __shared__ float As[2][8][128];
    __shared__ float Bs[2][8][128];

    int tid = threadIdx.x;
    int m0 = blockIdx.y * 128;
    int p0 = blockIdx.x * 128;
    int b  = blockIdx.z;

    const float* Bp = Bm + (size_t)b * strideB;

    int arow = tid >> 1;            // 0..127
    int acol = (tid & 1) * 4;       // 0 or 4
    int brow = tid >> 5;            // 0..7
    int bcol = (tid & 31) * 4;      // 0..124

    const float* Aptr = A  + (size_t)(m0 + arow) * K + acol;
    const float* Bptr = Bp + (size_t)brow * HW + p0 + bcol;

    // stage 0
    {
        float4 af = *(const float4*)Aptr;
        float4 bf = *(const float4*)Bptr;
        As[0][acol + 0][arow] = af.x;
        As[0][acol + 1][arow] = af.y;
        As[0][acol + 2][arow] = af.z;
        As[0][acol + 3][arow] = af.w;
        *(float4*)&Bs[0][brow][bcol] = bf;
    }
    __syncthreads();

    int ty = tid >> 4, tx = tid & 15;
    float acc[8][8];
#pragma unroll
    for (int i = 0; i < 8; i++)
#pragma unroll
        for (int j = 0; j < 8; j++) acc[i][j] = 0.f;

    int nk = K >> 3;
    for (int kt = 0; kt < nk; kt++) {
        int buf = kt & 1;
        float4 an, bn;
        bool has_next = (kt + 1 < nk);
        if (has_next) {
            an = *(const float4*)(Aptr + (kt + 1) * 8);
            bn = *(const float4*)(Bptr + (size_t)(kt + 1) * 8 * HW);
        }
#pragma unroll
        for (int kk = 0; kk < 8; kk++) {
            float4 a0 = *(float4*)&As[buf][kk][ty * 8];
            float4 a1 = *(float4*)&As[buf][kk][ty * 8 + 4];
            float4 b0 = *(float4*)&Bs[buf][kk][tx * 8];
            float4 b1 = *(float4*)&Bs[buf][kk][tx * 8 + 4];
            float a[8] = {a0.x, a0.y, a0.z, a0.w, a1.x, a1.y, a1.z, a1.w};
            float bb[8] = {b0.x, b0.y, b0.z, b0.w, b1.x, b1.y, b1.z, b1.w};
#pragma unroll
            for (int i = 0; i < 8; i++)
#pragma unroll
                for (int j = 0; j < 8; j++)
                    acc[i][j] += a[i] * bb[j];
        }
        if (has_next) {
            int nb = buf ^ 1;
            As[nb][acol + 0][arow] = an.x;
            As[nb][acol + 1][arow] = an.y;
            As[nb][acol + 2][arow] = an.z;
            As[nb][acol + 3][arow] = an.w;
            *(float4*)&Bs[nb][brow][bcol] = bn;
        }
        __syncthreads();
    }

    // epilogue
#pragma unroll
    for (int i = 0; i < 8; i++) {
        int m = m0 + ty * 8 + i;
        float bv = bias[m];
        size_t off = (size_t)b * strideC + (size_t)m * HW + p0 + tx * 8;
        float v[8];
#pragma unroll
        for (int j = 0; j < 8; j++) v[j] = acc[i][j] + bv;
        if (epi == 1) {
            const float* rp = Res + off;
            float4 r0 = *(const float4*)rp;
            float4 r1 = *(const float4*)(rp + 4);
            v[0] += r0.x; v[1] += r0.y; v[2] += r0.z; v[3] += r0.w;
            v[4] += r1.x; v[5] += r1.y; v[6] += r1.z; v[7] += r1.w;
        } else if (epi == 2) {
#pragma unroll
            for (int j = 0; j < 8; j++) v[j] = gelu_f(v[j]);
        }
        float4 o0 = make_float4(v[0], v[1], v[2], v[3]);
        float4 o1 = make_float4(v[4], v[5], v[6], v[7]);
        *(float4*)(C + off)     = o0;
        *(float4*)(C + off + 4) = o1;
    }
}

// ---------------- chunked attention: one block per (b, g) ----------------
// qkv layout: (b, m, p) with m = s*256 + c, s in {q,k,v}. Tokens of chunk g are p = g*64..g*64+63.
__global__ __launch_bounds__(256)
void attn_kernel(const float* __restrict__ qkv, float* __restrict__ out)
{
    extern __shared__ float sm[];
    float* QV = sm;                       // 256 x 65 (Q, then reused for V)
    float* Ks = sm + 256 * 65;            // 256 x 64
    float* Ss = sm + 256 * 65 + 256 * 64; // 64 x 65

    int g = blockIdx.x, b = blockIdx.y;
    int tid = threadIdx.x;
    const float* base = qkv + (size_t)b * 3 * CCH * HW + (size_t)g * CHUNK;

    // load Q, K (coalesced along tokens)
    for (int i = tid; i < 256 * 64; i += 256) {
        int c = i >> 6, t = i & 63;
        float qv = base[(size_t)c * HW + t];
        float kv = base[(size_t)(256 + c) * HW + t];
        QV[c * 65 + t] = qv;
        Ks[c * 64 + t] = kv;
    }
    __syncthreads();

    // S[i][j] = scale * sum_c Q[c][i] * K[c][j]
    {
        int ty = tid >> 4, tx = tid & 15;
        int i0 = ty * 4, j0 = tx * 4;
        float acc[4][4];
#pragma unroll
        for (int i = 0; i < 4; i++)
#pragma unroll
            for (int j = 0; j < 4; j++) acc[i][j] = 0.f;

        for (int c = 0; c < 256; c++) {
            float a0 = QV[c * 65 + i0 + 0];
            float a1 = QV[c * 65 + i0 + 1];
            float a2 = QV[c * 65 + i0 + 2];
            float a3 = QV[c * 65 + i0 + 3];
            float4 bv = *(float4*)&Ks[c * 64 + j0];
            float bb[4] = {bv.x, bv.y, bv.z, bv.w};
            float aa[4] = {a0, a1, a2, a3};
#pragma unroll
            for (int i = 0; i < 4; i++)
#pragma unroll
                for (int j = 0; j < 4; j++)
                    acc[i][j] += aa[i] * bb[j];
        }
        const float scale = 0.0625f;  // 256^-0.5
#pragma unroll
        for (int i = 0; i < 4; i++)
#pragma unroll
            for (int j = 0; j < 4; j++)
                Ss[(i0 + i) * 65 + j0 + j] = acc[i][j] * scale;
    }
    __syncthreads();

    // load V into QV (Q no longer needed), then softmax rows of Ss
    for (int i = tid; i < 256 * 64; i += 256) {
        int c = i >> 6, t = i & 63;
        QV[c * 65 + t] = base[(size_t)(512 + c) * HW + t];
    }
    {
        int r = tid >> 2, q4 = tid & 3;
        float* row = Ss + r * 65;
        float mx = -1e30f;
#pragma unroll
        for (int j = 0; j < 16; j++) mx = fmaxf(mx, row[q4 * 16 + j]);
        mx = fmaxf(mx, __shfl_xor_sync(0xffffffffu, mx, 1));
        mx = fmaxf(mx, __shfl_xor_sync(0xffffffffu, mx, 2));
        float e[16];
        float s = 0.f;
#pragma unroll
        for (int j = 0; j < 16; j++) {
            e[j] = expf(row[q4 * 16 + j] - mx);
            s += e[j];
        }
        s += __shfl_xor_sync(0xffffffffu, s, 1);
        s += __shfl_xor_sync(0xffffffffu, s, 2);
        float inv = 1.0f / s;
#pragma unroll
        for (int j = 0; j < 16; j++) row[q4 * 16 + j] = e[j] * inv;
    }
    __syncthreads();

    // O[c][i] = sum_j V[c][j] * P[i][j]   (8x8 register tile per thread)
    {
        int cg = tid >> 3;        // 0..31 -> c0
        int ig = tid & 7;         // 0..7  -> i0
        int c0 = cg * 8, i0 = ig * 8;
        float o[8][8];
#pragma unroll
        for (int k = 0; k < 8; k++)
#pragma unroll
            for (int l = 0; l < 8; l++) o[k][l] = 0.f;

        for (int j = 0; j < 64; j++) {
            float v[8], p[8];
#pragma unroll
            for (int k = 0; k < 8; k++) v[k] = QV[(c0 + k) * 65 + j];
#pragma unroll
            for (int k = 0; k < 8; k++) p[k] = Ss[(i0 + k) * 65 + j];
#pragma unroll
            for (int k = 0; k < 8; k++)
#pragma unroll
                for (int l = 0; l < 8; l++)
                    o[k][l] += v[k] * p[l];
        }
        float* op = out + (size_t)b * CCH * HW + (size_t)g * CHUNK;
#pragma unroll
        for (int k = 0; k < 8; k++) {
            float4 u0 = make_float4(o[k][0], o[k][1], o[k][2], o[k][3]);
            float4 u1 = make_float4(o[k][4], o[k][5], o[k][6], o[k][7]);
            float* dst = op + (size_t)(c0 + k) * HW + i0;
            *(float4*)dst       = u0;
            *(float4*)(dst + 4) = u1;
        }
    }
}

// ---------------- depthwise 3x3 conv + bias + gelu ----------------
__global__ void dwconv_kernel(const float* __restrict__ in,
                              const float* __restrict__ w,
                              const float* __restrict__ bias,
                              float* __restrict__ out)
{
    int idx = blockIdx.x * 256 + threadIdx.x;   // over BATCH*HID*HW
    int x = idx & 127;
    int y = (idx >> 7) & 127;
    int c = (idx >> 14) & (HID - 1);
    int b = idx >> 23;
    const float* ip = in + ((size_t)(b * HID + c) << 14);
    const float* wp = w + c * 9;

    float acc = 0.f;
#pragma unroll
    for (int ky = 0; ky < 3; ky++) {
        int yy = y + ky - 1;
        if (yy < 0 || yy > 127) continue;
#pragma unroll
        for (int kx = 0; kx < 3; kx++) {
            int xx = x + kx - 1;
            if (xx < 0 || xx > 127) continue;
            acc += ip[yy * 128 + xx] * wp[ky * 3 + kx];
        }
    }
    acc += bias[c];
    out[idx] = gelu_f(acc);
}

// ---------------- launcher ----------------
extern "C" void kernel_launch(void* const* d_in, const int* in_sizes, int n_in,
                              void* d_out, int out_size)
{
    const float* x       = (const float*)d_in[0];
    const float* ln1_s   = (const float*)d_in[1];
    const float* ln1_b   = (const float*)d_in[2];
    const float* qkv_w   = (const float*)d_in[3];
    const float* qkv_b   = (const float*)d_in[4];
    const float* proj_w  = (const float*)d_in[5];
    const float* proj_b  = (const float*)d_in[6];
    const float* ln2_s   = (const float*)d_in[7];
    const float* ln2_b   = (const float*)d_in[8];
    const float* conv1_w = (const float*)d_in[9];
    const float* conv1_b = (const float*)d_in[10];
    const float* conv2_w = (const float*)d_in[11];
    const float* conv2_b = (const float*)d_in[12];
    const float* conv3_w = (const float*)d_in[13];
    const float* conv3_b = (const float*)d_in[14];
    float* outp = (float*)d_out;

    float *xln, *qkv, *attn, *x2, *h1, *h2;
    cudaGetSymbolAddress((void**)&xln,  g_xln);
    cudaGetSymbolAddress((void**)&qkv,  g_qkv);
    cudaGetSymbolAddress((void**)&attn, g_attn);
    cudaGetSymbolAddress((void**)&x2,   g_x2);
    cudaGetSymbolAddress((void**)&h1,   g_h1);
    cudaGetSymbolAddress((void**)&h2,   g_h2);

    const int ATTN_SMEM = (256 * 65 + 256 * 64 + 64 * 65) * 4;  // 148736 B
    cudaFuncSetAttribute(attn_kernel, cudaFuncAttributeMaxDynamicSharedMemorySize, ATTN_SMEM);

    // 1) LN1 (NCHW in/out)
    ln_kernel<<<BATCH * HW / 256, 256>>>(x, ln1_s, ln1_b, xln);

    // 2) QKV GEMM: (768x256) @ xln
    sgemm_kernel<<<dim3(HW / 128, 6, BATCH), 256>>>(
        qkv_w, xln, qkv_b, nullptr, qkv, 256,
        (long)CCH * HW, (long)3 * CCH * HW, 0);

    // 3) chunked attention
    attn_kernel<<<dim3(NG, BATCH), 256, ATTN_SMEM>>>(qkv, attn);

    // 4) proj GEMM + residual(x) -> x2
    sgemm_kernel<<<dim3(HW / 128, 2, BATCH), 256>>>(
        proj_w, attn, proj_b, x, x2, 256,
        (long)CCH * HW, (long)CCH * HW, 1);

    // 5) LN2 -> xln (reuse)
    ln_kernel<<<BATCH * HW / 256, 256>>>(x2, ln2_s, ln2_b, xln);

    // 6) conv1 (1x1) GEMM + bias + gelu -> h1
    sgemm_kernel<<<dim3(HW / 128, 4, BATCH), 256>>>(
        conv1_w, xln, conv1_b, nullptr, h1, 256,
        (long)CCH * HW, (long)HID * HW, 2);

    // 7) depthwise 3x3 + bias + gelu -> h2
    dwconv_kernel<<<BATCH * HID * HW / 256, 256>>>(h1, conv2_w, conv2_b, h2);

    // 8) conv3 (1x1) GEMM + bias + residual(x2) -> out
    sgemm_kernel<<<dim3(HW / 128, 2, BATCH), 256>>>(
        conv3_w, h2, conv3_b, x2, outp, 512,
        (long)HID * HW, (long)CCH * HW, 1);
}

// round 3
// speedup vs baseline: 2.4998x; 2.4998x over previous
#include <cuda_runtime.h>
#include <cuda_bf16.h>
#include <cstdint>
#include <cstddef>
#include <math.h>

// Problem constants
#define BATCH 8
#define CCH   256        // channels C
#define HW    16384      // H*W = 128*128
#define HID   512        // hidden = 2*C
#define CHUNK 64
#define NG    (HW / CHUNK)   // 256 chunks per image

// GEMM tiling
#define BM 128
#define BN 128
#define BK 32
#define ASTRIDE 40       // bf16 elems per A smem row (80B rows, 16B-aligned)
#define BSTRIDE 136      // bf16 elems per B smem row (272B rows, 16B-aligned)
#define ASZ_BYTES (BM * ASTRIDE * 2)   // 10240
#define BSZ_BYTES (BK * BSTRIDE * 2)   // 8704

// ---------------- scratch (module-load allocated, allowed) ----------------
__device__ __nv_bfloat16 g_xln [BATCH * CCH * HW];       // LN1/LN2 out (bf16, NCHW)
__device__ __nv_bfloat16 g_qkv [BATCH * 3 * CCH * HW];   // (b, m=0..767, p) bf16
__device__ __nv_bfloat16 g_attn[BATCH * CCH * HW];       // attention output bf16
__device__ float         g_x2  [BATCH * CCH * HW];       // x + attn (fp32)
__device__ __nv_bfloat16 g_h1  [BATCH * HID * HW];       // conv1+gelu out bf16
__device__ __nv_bfloat16 g_h2  [BATCH * HID * HW];       // dwconv+gelu out bf16
__device__ __nv_bfloat16 g_wbf [768*256 + 256*256 + 512*256 + 256*512];

__device__ __forceinline__ float gelu_f(float v) {
    return 0.5f * v * (1.0f + erff(v * 0.70710678118654752f));
}

union BF2U { __nv_bfloat162 h; unsigned int u; };

__device__ __forceinline__ unsigned int pack_bf2(float a, float b) {
    BF2U t; t.h = __floats2bfloat162_rn(a, b); return t.u;
}

// ---------------- helpers: ldmatrix / mma / cp.async ----------------
__device__ __forceinline__ void ldsm_x4(unsigned int* r, unsigned int addr) {
    asm volatile("ldmatrix.sync.aligned.m8n8.x4.shared.b16 {%0,%1,%2,%3}, [%4];"
                 : "=r"(r[0]), "=r"(r[1]), "=r"(r[2]), "=r"(r[3]) : "r"(addr));
}
__device__ __forceinline__ void ldsm_x4_t(unsigned int* r, unsigned int addr) {
    asm volatile("ldmatrix.sync.aligned.m8n8.x4.trans.shared.b16 {%0,%1,%2,%3}, [%4];"
                 : "=r"(r[0]), "=r"(r[1]), "=r"(r[2]), "=r"(r[3]) : "r"(addr));
}
__device__ __forceinline__ void mma_bf16(float* d, const unsigned int* a, const unsigned int* b) {
    asm volatile("mma.sync.aligned.m16n8k16.row.col.f32.bf16.bf16.f32 "
                 "{%0,%1,%2,%3}, {%4,%5,%6,%7}, {%8,%9}, {%0,%1,%2,%3};"
                 : "+f"(d[0]), "+f"(d[1]), "+f"(d[2]), "+f"(d[3])
                 : "r"(a[0]), "r"(a[1]), "r"(a[2]), "r"(a[3]), "r"(b[0]), "r"(b[1]));
}
__device__ __forceinline__ void cp_async16(unsigned int dst, const void* src) {
    asm volatile("cp.async.cg.shared.global [%0], [%1], 16;" :: "r"(dst), "l"(src));
}
__device__ __forceinline__ void cp_commit() {
    asm volatile("cp.async.commit_group;" ::: "memory");
}
__device__ __forceinline__ void cp_wait0() {
    asm volatile("cp.async.wait_group 0;" ::: "memory");
}

// ---------------- weight fp32 -> bf16 ----------------
__global__ void cvt_kernel(const float* __restrict__ src, __nv_bfloat16* __restrict__ dst, int n) {
    int i = blockIdx.x * 256 + threadIdx.x;
    if (i < n) dst[i] = __float2bfloat16(src[i]);
}

// ---------------- LayerNorm over channels at each (b, p): fp32 in -> bf16 out ----
__global__ void ln_kernel(const float* __restrict__ in,
                          const float* __restrict__ scale,
                          const float* __restrict__ bias,
                          __nv_bfloat16* __restrict__ out)
{
    int gid = blockIdx.x * blockDim.x + threadIdx.x;   // over BATCH*HW
    int b = gid >> 14;
    int p = gid & (HW - 1);
    const float* ip = in + (size_t)b * CCH * HW + p;
    __nv_bfloat16* op = out + (size_t)b * CCH * HW + p;

    float s = 0.f, s2 = 0.f;
#pragma unroll 8
    for (int c = 0; c < CCH; c++) {
        float v = ip[(size_t)c * HW];
        s += v; s2 += v * v;
    }
    float mu  = s  * (1.0f / CCH);
    float var = s2 * (1.0f / CCH) - mu * mu;
    float r   = rsqrtf(var + 1e-5f);
#pragma unroll 8
    for (int c = 0; c < CCH; c++) {
        float v = ip[(size_t)c * HW];
        op[(size_t)c * HW] = __float2bfloat16((v - mu) * r * scale[c] + bias[c]);
    }
}

// ---------------- bf16 tensor-core GEMM ----------------
// C[b][m][p] = sum_k A[m][k] * B[b][k][p]  (A bf16 row-major MxK, B bf16 per-batch KxHW)
// epi: 0 = +bias -> bf16 out ; 1 = +bias + Res(fp32) -> fp32 out ; 2 = gelu(+bias) -> bf16 out
__global__ __launch_bounds__(256, 2)
void gemm_bf16_kernel(const __nv_bfloat16* __restrict__ A,
                      const __nv_bfloat16* __restrict__ Bact,
                      const float* __restrict__ bias,
                      const float* __restrict__ Res,
                      void* __restrict__ Cout,
                      int K, long strideB, long strideC, int epi)
{
    __shared__ __nv_bfloat16 As[2][BM * ASTRIDE];
    __shared__ __nv_bfloat16 Bs[2][BK * BSTRIDE];

    int tid = threadIdx.x;
    int m0 = blockIdx.y * BM;
    int p0 = blockIdx.x * BN;
    int b  = blockIdx.z;
    const __nv_bfloat16* Bp = Bact + (size_t)b * strideB;

    const __nv_bfloat16* Aptr0 = A + (size_t)(m0 + (tid >> 2)) * K + (tid & 3) * 8;
    const __nv_bfloat16* Aptr1 = A + (size_t)(m0 + 64 + (tid >> 2)) * K + (tid & 3) * 8;
    const __nv_bfloat16* Bptr0 = Bp + (size_t)(tid >> 4) * HW + p0 + (tid & 15) * 8;
    const __nv_bfloat16* Bptr1 = Bp + (size_t)(16 + (tid >> 4)) * HW + p0 + (tid & 15) * 8;

    unsigned int as_base = (unsigned int)__cvta_generic_to_shared(&As[0][0]);
    unsigned int bs_base = (unsigned int)__cvta_generic_to_shared(&Bs[0][0]);

    unsigned int sa0 = as_base + ((tid >> 2) * ASTRIDE + (tid & 3) * 8) * 2;
    unsigned int sa1 = as_base + ((64 + (tid >> 2)) * ASTRIDE + (tid & 3) * 8) * 2;
    unsigned int sb0 = bs_base + ((tid >> 4) * BSTRIDE + (tid & 15) * 8) * 2;
    unsigned int sb1 = bs_base + ((16 + (tid >> 4)) * BSTRIDE + (tid & 15) * 8) * 2;

    cp_async16(sa0, Aptr0);
    cp_async16(sa1, Aptr1);
    cp_async16(sb0, Bptr0);
    cp_async16(sb1, Bptr1);
    cp_commit();
    cp_wait0();
    __syncthreads();

    int warp = tid >> 5, lane = tid & 31;
    int wm = warp >> 2;          // 0..1 : warp covers 64 m-rows
    int wn = warp & 3;           // 0..3 : warp covers 32 n-cols

    float acc[4][4][4];
#pragma unroll
    for (int i = 0; i < 4; i++)
#pragma unroll
        for (int j = 0; j < 4; j++)
#pragma unroll
            for (int q = 0; q < 4; q++) acc[i][j][q] = 0.f;

    int a_row = wm * 64 + (lane & 15);
    int a_col = (lane >> 4) * 8;
    int b_row = (lane & 15);
    int b_col = wn * 32 + (lane >> 4) * 8;

    int nk = K >> 5;
    for (int kt = 0; kt < nk; kt++) {
        int buf = kt & 1;
        bool nxt = (kt + 1 < nk);
        if (nxt) {
            unsigned int ao = (buf ^ 1) * ASZ_BYTES;
            unsigned int bo = (buf ^ 1) * BSZ_BYTES;
            cp_async16(sa0 + ao, Aptr0 + (kt + 1) * BK);
            cp_async16(sa1 + ao, Aptr1 + (kt + 1) * BK);
            cp_async16(sb0 + bo, Bptr0 + (size_t)(kt + 1) * BK * HW);
            cp_async16(sb1 + bo, Bptr1 + (size_t)(kt + 1) * BK * HW);
            cp_commit();
        }

        unsigned int abase = as_base + buf * ASZ_BYTES;
        unsigned int bbase = bs_base + buf * BSZ_BYTES;
#pragma unroll
        for (int kk = 0; kk < 2; kk++) {
            unsigned int af[4][4];
            unsigned int bfr[2][4];
#pragma unroll
            for (int i = 0; i < 4; i++)
                ldsm_x4(af[i], abase + (((a_row + i * 16) * ASTRIDE) + a_col + kk * 16) * 2);
#pragma unroll
            for (int j = 0; j < 2; j++)
                ldsm_x4_t(bfr[j], bbase + (((b_row + kk * 16) * BSTRIDE) + b_col + j * 16) * 2);
#pragma unroll
            for (int i = 0; i < 4; i++)
#pragma unroll
                for (int jn = 0; jn < 4; jn++)
                    mma_bf16(acc[i][jn], af[i], &bfr[jn >> 1][(jn & 1) * 2]);
        }

        if (nxt) cp_wait0();
        __syncthreads();
    }

    int l4 = lane >> 2, l2 = (lane & 3) * 2;
#pragma unroll
    for (int i = 0; i < 4; i++) {
        int r0 = m0 + wm * 64 + i * 16 + l4;
        int r1 = r0 + 8;
        float bv0 = bias[r0], bv1 = bias[r1];
#pragma unroll
        for (int jn = 0; jn < 4; jn++) {
            int col = p0 + wn * 32 + jn * 8 + l2;
            size_t off0 = (size_t)b * strideC + (size_t)r0 * HW + col;
            size_t off1 = (size_t)b * strideC + (size_t)r1 * HW + col;
            float v0 = acc[i][jn][0] + bv0;
            float v1 = acc[i][jn][1] + bv0;
            float v2 = acc[i][jn][2] + bv1;
            float v3 = acc[i][jn][3] + bv1;
            if (epi == 1) {
                float* Cf = (float*)Cout;
                float2 q0 = *(const float2*)(Res + off0);
                float2 q1 = *(const float2*)(Res + off1);
                *(float2*)(Cf + off0) = make_float2(v0 + q0.x, v1 + q0.y);
                *(float2*)(Cf + off1) = make_float2(v2 + q1.x, v3 + q1.y);
            } else {
                if (epi == 2) {
                    v0 = gelu_f(v0); v1 = gelu_f(v1);
                    v2 = gelu_f(v2); v3 = gelu_f(v3);
                }
                __nv_bfloat16* Cb = (__nv_bfloat16*)Cout;
                unsigned int* p32a = (unsigned int*)(Cb + off0);
                unsigned int* p32b = (unsigned int*)(Cb + off1);
                *p32a = pack_bf2(v0, v1);
                *p32b = pack_bf2(v2, v3);
            }
        }
    }
}

// ---------------- chunked attention: one block per (b, g), bf16 in/out ----------
__global__ __launch_bounds__(256)
void attn_kernel(const __nv_bfloat16* __restrict__ qkv, __nv_bfloat16* __restrict__ out)
{
    extern __shared__ float sm[];
    float* QV = sm;                       // 256 x 65 (Q, then reused for V)
    float* Ks = sm + 256 * 65;            // 256 x 64
    float* Ss = sm + 256 * 65 + 256 * 64; // 64 x 65

    int g = blockIdx.x, b = blockIdx.y;
    int tid = threadIdx.x;
    const __nv_bfloat16* base = qkv + (size_t)b * 3 * CCH * HW + (size_t)g * CHUNK;

    for (int i = tid; i < 256 * 64; i += 256) {
        int c = i >> 6, t = i & 63;
        QV[c * 65 + t] = __bfloat162float(base[(size_t)c * HW + t]);
        Ks[c * 64 + t] = __bfloat162float(base[(size_t)(256 + c) * HW + t]);
    }
    __syncthreads();

    // S[i][j] = scale * sum_c Q[c][i] * K[c][j]
    {
        int ty = tid >> 4, tx = tid & 15;
        int i0 = ty * 4, j0 = tx * 4;
        float acc[4][4];
#pragma unroll
        for (int i = 0; i < 4; i++)
#pragma unroll
            for (int j = 0; j < 4; j++) acc[i][j] = 0.f;

        for (int c = 0; c < 256; c++) {
            float aa[4];
            aa[0] = QV[c * 65 + i0 + 0];
            aa[1] = QV[c * 65 + i0 + 1];
            aa[2] = QV[c * 65 + i0 + 2];
            aa[3] = QV[c * 65 + i0 + 3];
            float4 bv = *(float4*)&Ks[c * 64 + j0];
            float bb[4] = {bv.x, bv.y, bv.z, bv.w};
#pragma unroll
            for (int i = 0; i < 4; i++)
#pragma unroll
                for (int j = 0; j < 4; j++)
                    acc[i][j] += aa[i] * bb[j];
        }
        const float scale = 0.0625f;
#pragma unroll
        for (int i = 0; i < 4; i++)
#pragma unroll
            for (int j = 0; j < 4; j++)
                Ss[(i0 + i) * 65 + j0 + j] = acc[i][j] * scale;
    }
    __syncthreads();

    // load V into QV (Q dead), softmax rows of Ss
    for (int i = tid; i < 256 * 64; i += 256) {
        int c = i >> 6, t = i & 63;
        QV[c * 65 + t] = __bfloat162float(base[(size_t)(512 + c) * HW + t]);
    }
    {
        int r = tid >> 2, q4 = tid & 3;
        float* row = Ss + r * 65;
        float mx = -1e30f;
#pragma unroll
        for (int j = 0; j < 16; j++) mx = fmaxf(mx, row[q4 * 16 + j]);
        mx = fmaxf(mx, __shfl_xor_sync(0xffffffffu, mx, 1));
        mx = fmaxf(mx, __shfl_xor_sync(0xffffffffu, mx, 2));
        float e[16];
        float s = 0.f;
#pragma unroll
        for (int j = 0; j < 16; j++) {
            e[j] = expf(row[q4 * 16 + j] - mx);
            s += e[j];
        }
        s += __shfl_xor_sync(0xffffffffu, s, 1);
        s += __shfl_xor_sync(0xffffffffu, s, 2);
        float inv = 1.0f / s;
#pragma unroll
        for (int j = 0; j < 16; j++) row[q4 * 16 + j] = e[j] * inv;
    }
    __syncthreads();

    // O[c][i] = sum_j V[c][j] * P[i][j]
    {
        int cg = tid >> 3;
        int ig = tid & 7;
        int c0 = cg * 8, i0 = ig * 8;
        float o[8][8];
#pragma unroll
        for (int k = 0; k < 8; k++)
#pragma unroll
            for (int l = 0; l < 8; l++) o[k][l] = 0.f;

        for (int j = 0; j < 64; j++) {
            float v[8], p[8];
#pragma unroll
            for (int k = 0; k < 8; k++) v[k] = QV[(c0 + k) * 65 + j];
#pragma unroll
            for (int k = 0; k < 8; k++) p[k] = Ss[(i0 + k) * 65 + j];
#pragma unroll
            for (int k = 0; k < 8; k++)
#pragma unroll
                for (int l = 0; l < 8; l++)
                    o[k][l] += v[k] * p[l];
        }
        __nv_bfloat16* op = out + (size_t)b * CCH * HW + (size_t)g * CHUNK;
#pragma unroll
        for (int k = 0; k < 8; k++) {
            uint4 vv;
            vv.x = pack_bf2(o[k][0], o[k][1]);
            vv.y = pack_bf2(o[k][2], o[k][3]);
            vv.z = pack_bf2(o[k][4], o[k][5]);
            vv.w = pack_bf2(o[k][6], o[k][7]);
            *(uint4*)(op + (size_t)(c0 + k) * HW + i0) = vv;
        }
    }
}

// ---------------- depthwise 3x3 conv + bias + gelu (bf16 in/out) ----------------
__global__ void dwconv_kernel(const __nv_bfloat16* __restrict__ in,
                              const float* __restrict__ w,
                              const float* __restrict__ bias,
                              __nv_bfloat16* __restrict__ out)
{
    int idx = blockIdx.x * 256 + threadIdx.x;   // over BATCH*HID*HW
    int x = idx & 127;
    int y = (idx >> 7) & 127;
    int c = (idx >> 14) & (HID - 1);
    const __nv_bfloat16* ip = in + ((size_t)(idx >> 14) << 14);
    const float* wp = w + c * 9;

    float acc = 0.f;
#pragma unroll
    for (int ky = 0; ky < 3; ky++) {
        int yy = y + ky - 1;
        if (yy < 0 || yy > 127) continue;
#pragma unroll
        for (int kx = 0; kx < 3; kx++) {
            int xx = x + kx - 1;
            if (xx < 0 || xx > 127) continue;
            acc += __bfloat162float(ip[yy * 128 + xx]) * wp[ky * 3 + kx];
        }
    }
    acc += bias[c];
    out[idx] = __float2bfloat16(gelu_f(acc));
}

// ---------------- launcher ----------------
extern "C" void kernel_launch(void* const* d_in, const int* in_sizes, int n_in,
                              void* d_out, int out_size)
{
    const float* x       = (const float*)d_in[0];
    const float* ln1_s   = (const float*)d_in[1];
    const float* ln1_b   = (const float*)d_in[2];
    const float* qkv_w   = (const float*)d_in[3];
    const float* qkv_b   = (const float*)d_in[4];
    const float* proj_w  = (const float*)d_in[5];
    const float* proj_b  = (const float*)d_in[6];
    const float* ln2_s   = (const float*)d_in[7];
    const float* ln2_b   = (const float*)d_in[8];
    const float* conv1_w = (const float*)d_in[9];
    const float* conv1_b = (const float*)d_in[10];
    const float* conv2_w = (const float*)d_in[11];
    const float* conv2_b = (const float*)d_in[12];
    const float* conv3_w = (const float*)d_in[13];
    const float* conv3_b = (const float*)d_in[14];
    float* outp = (float*)d_out;

    __nv_bfloat16 *xln, *qkv, *attnp, *h1, *h2, *wbf;
    float *x2;
    cudaGetSymbolAddress((void**)&xln,   g_xln);
    cudaGetSymbolAddress((void**)&qkv,   g_qkv);
    cudaGetSymbolAddress((void**)&attnp, g_attn);
    cudaGetSymbolAddress((void**)&x2,    g_x2);
    cudaGetSymbolAddress((void**)&h1,    g_h1);
    cudaGetSymbolAddress((void**)&h2,    g_h2);
    cudaGetSymbolAddress((void**)&wbf,   g_wbf);

    __nv_bfloat16* w_qkv = wbf;
    __nv_bfloat16* w_prj = w_qkv + 768 * 256;
    __nv_bfloat16* w_c1  = w_prj + 256 * 256;
    __nv_bfloat16* w_c3  = w_c1 + 512 * 256;

    const int ATTN_SMEM = (256 * 65 + 256 * 64 + 64 * 65) * 4;  // 148736 B
    cudaFuncSetAttribute(attn_kernel, cudaFuncAttributeMaxDynamicSharedMemorySize, ATTN_SMEM);

    // 0) weight conversions (tiny)
    cvt_kernel<<<(768 * 256 + 255) / 256, 256>>>(qkv_w,  w_qkv, 768 * 256);
    cvt_kernel<<<(256 * 256 + 255) / 256, 256>>>(proj_w, w_prj, 256 * 256);
    cvt_kernel<<<(512 * 256 + 255) / 256, 256>>>(conv1_w, w_c1, 512 * 256);
    cvt_kernel<<<(256 * 512 + 255) / 256, 256>>>(conv3_w, w_c3, 256 * 512);

    // 1) LN1: x fp32 -> xln bf16
    ln_kernel<<<BATCH * HW / 256, 256>>>(x, ln1_s, ln1_b, xln);

    // 2) QKV GEMM -> qkv bf16
    gemm_bf16_kernel<<<dim3(HW / BN, 768 / BM, BATCH), 256>>>(
        w_qkv, xln, qkv_b, nullptr, qkv, 256,
        (long)CCH * HW, (long)3 * CCH * HW, 0);

    // 3) chunked attention -> attn bf16
    attn_kernel<<<dim3(NG, BATCH), 256, ATTN_SMEM>>>(qkv, attnp);

    // 4) proj GEMM + residual(x fp32) -> x2 fp32
    gemm_bf16_kernel<<<dim3(HW / BN, 256 / BM, BATCH), 256>>>(
        w_prj, attnp, proj_b, x, x2, 256,
        (long)CCH * HW, (long)CCH * HW, 1);

    // 5) LN2: x2 fp32 -> xln bf16 (reuse)
    ln_kernel<<<BATCH * HW / 256, 256>>>(x2, ln2_s, ln2_b, xln);

    // 6) conv1 (1x1) + gelu -> h1 bf16
    gemm_bf16_kernel<<<dim3(HW / BN, 512 / BM, BATCH), 256>>>(
        w_c1, xln, conv1_b, nullptr, h1, 256,
        (long)CCH * HW, (long)HID * HW, 2);

    // 7) depthwise 3x3 + gelu -> h2 bf16
    dwconv_kernel<<<BATCH * HID * HW / 256, 256>>>(h1, conv2_w, conv2_b, h2);

    // 8) conv3 (1x1) + residual(x2 fp32) -> out fp32
    gemm_bf16_kernel<<<dim3(HW / BN, 256 / BM, BATCH), 256>>>(
        w_c3, h2, conv3_b, x2, outp, 512,
        (long)HID * HW, (long)CCH * HW, 1);
}

// round 4
// speedup vs baseline: 3.5930x; 1.4373x over previous
#include <cuda_runtime.h>
#include <cuda_bf16.h>
#include <cstdint>
#include <cstddef>
#include <math.h>

// Problem constants
#define BATCH 8
#define CCH   256        // channels C
#define HW    16384      // H*W = 128*128
#define HID   512        // hidden = 2*C
#define CHUNK 64
#define NG    (HW / CHUNK)   // 256 chunks per image

// GEMM tiling
#define BM 128
#define BN 128
#define BK 32
#define ASTRIDE 40
#define BSTRIDE 136
#define ASZ_BYTES (BM * ASTRIDE * 2)   // 10240
#define BSZ_BYTES (BK * BSTRIDE * 2)   // 8704

// attention smem layout (bf16 elems), row stride 72
#define ATS 72
#define AT_QV 0
#define AT_K  (256 * ATS)            // 18432
#define AT_P  (512 * ATS)            // 36864
#define AT_ELEMS (512 * ATS + 64 * ATS)   // 41472 elems -> 82944 B
#define AT_SMEM_BYTES (AT_ELEMS * 2)

// LN smem: 256x65 fp32 tile + mus[64] + rs[64]
#define LN_SMEM_BYTES (256 * 65 * 4 + 128 * 4)

// ---------------- scratch ----------------
__device__ __nv_bfloat16 g_xln [BATCH * CCH * HW];
__device__ __nv_bfloat16 g_qkv [BATCH * 3 * CCH * HW];
__device__ __nv_bfloat16 g_attn[BATCH * CCH * HW];
__device__ float         g_x2  [BATCH * CCH * HW];
__device__ __nv_bfloat16 g_h1  [BATCH * HID * HW];
__device__ __nv_bfloat16 g_h2  [BATCH * HID * HW];
__device__ __nv_bfloat16 g_wbf [768*256 + 256*256 + 512*256 + 256*512];

__device__ __forceinline__ float gelu_f(float v) {
    return 0.5f * v * (1.0f + erff(v * 0.70710678118654752f));
}

union BF2U { __nv_bfloat162 h; unsigned int u; };
__device__ __forceinline__ unsigned int pack_bf2(float a, float b) {
    BF2U t; t.h = __floats2bfloat162_rn(a, b); return t.u;
}

// ---------------- helpers ----------------
__device__ __forceinline__ void ldsm_x4(unsigned int* r, unsigned int addr) {
    asm volatile("ldmatrix.sync.aligned.m8n8.x4.shared.b16 {%0,%1,%2,%3}, [%4];"
                 : "=r"(r[0]), "=r"(r[1]), "=r"(r[2]), "=r"(r[3]) : "r"(addr));
}
__device__ __forceinline__ void ldsm_x4_t(unsigned int* r, unsigned int addr) {
    asm volatile("ldmatrix.sync.aligned.m8n8.x4.trans.shared.b16 {%0,%1,%2,%3}, [%4];"
                 : "=r"(r[0]), "=r"(r[1]), "=r"(r[2]), "=r"(r[3]) : "r"(addr));
}
__device__ __forceinline__ void mma_bf16(float* d, const unsigned int* a, const unsigned int* b) {
    asm volatile("mma.sync.aligned.m16n8k16.row.col.f32.bf16.bf16.f32 "
                 "{%0,%1,%2,%3}, {%4,%5,%6,%7}, {%8,%9}, {%0,%1,%2,%3};"
                 : "+f"(d[0]), "+f"(d[1]), "+f"(d[2]), "+f"(d[3])
                 : "r"(a[0]), "r"(a[1]), "r"(a[2]), "r"(a[3]), "r"(b[0]), "r"(b[1]));
}
__device__ __forceinline__ void cp_async16(unsigned int dst, const void* src) {
    asm volatile("cp.async.cg.shared.global [%0], [%1], 16;" :: "r"(dst), "l"(src));
}
__device__ __forceinline__ void cp_commit() {
    asm volatile("cp.async.commit_group;" ::: "memory");
}
__device__ __forceinline__ void cp_wait0() {
    asm volatile("cp.async.wait_group 0;" ::: "memory");
}

// ---------------- merged weight fp32 -> bf16 ----------------
// segments: qkv 196608, proj 65536, conv1 131072, conv3 131072 (total 524288)
__global__ void cvt_all_kernel(const float* __restrict__ s0, const float* __restrict__ s1,
                               const float* __restrict__ s2, const float* __restrict__ s3,
                               __nv_bfloat16* __restrict__ dst)
{
    int i = blockIdx.x * 256 + threadIdx.x;
    const float* s; int off;
    if (i < 196608)      { s = s0; off = i; }
    else if (i < 262144) { s = s1; off = i - 196608; }
    else if (i < 393216) { s = s2; off = i - 262144; }
    else                 { s = s3; off = i - 393216; }
    dst[i] = __float2bfloat16(s[off]);
}

// ---------------- single-pass LayerNorm: fp32 in -> bf16 out ----------------
// one block per (b, 64-position tile); smem-buffered so DRAM is read once.
__global__ __launch_bounds__(256)
void ln_kernel(const float* __restrict__ in,
               const float* __restrict__ scale,
               const float* __restrict__ bias,
               __nv_bfloat16* __restrict__ out)
{
    extern __shared__ float lns[];
    float* ts  = lns;              // [256][65]
    float* mus = lns + 256 * 65;   // [64]
    float* rs  = mus + 64;         // [64]

    int bp = blockIdx.x;           // 0 .. BATCH*256-1
    int b  = bp >> 8;
    int p0 = (bp & 255) * 64;
    int tid = threadIdx.x;
    const float* ip = in + (size_t)b * CCH * HW + p0;

    // load 256c x 64p (coalesced: 64 consecutive threads per channel row)
#pragma unroll
    for (int k = 0; k < 64; k++) {
        int e = k * 256 + tid;
        int c = e >> 6, p = e & 63;
        ts[c * 65 + p] = ip[(size_t)c * HW + p];
    }
    __syncthreads();

    // reduce: 4 threads per position
    {
        int tq = tid & 3, pp = tid >> 2;
        float s = 0.f, s2 = 0.f;
#pragma unroll 16
        for (int j = 0; j < 64; j++) {
            float v = ts[(tq + 4 * j) * 65 + pp];
            s += v; s2 += v * v;
        }
        s  += __shfl_xor_sync(0xffffffffu, s, 1);
        s  += __shfl_xor_sync(0xffffffffu, s, 2);
        s2 += __shfl_xor_sync(0xffffffffu, s2, 1);
        s2 += __shfl_xor_sync(0xffffffffu, s2, 2);
        float mu  = s * (1.0f / CCH);
        float var = s2 * (1.0f / CCH) - mu * mu;
        if (tq == 0) { mus[pp] = mu; rs[pp] = rsqrtf(var + 1e-5f); }
    }
    __syncthreads();

    __nv_bfloat16* op = out + (size_t)b * CCH * HW + p0;
#pragma unroll
    for (int k = 0; k < 64; k++) {
        int e = k * 256 + tid;
        int c = e >> 6, p = e & 63;
        float v = ts[c * 65 + p];
        op[(size_t)c * HW + p] = __float2bfloat16((v - mus[p]) * rs[p] * scale[c] + bias[c]);
    }
}

// ---------------- bf16 tensor-core GEMM (unchanged from R3) ----------------
__global__ __launch_bounds__(256, 2)
void gemm_bf16_kernel(const __nv_bfloat16* __restrict__ A,
                      const __nv_bfloat16* __restrict__ Bact,
                      const float* __restrict__ bias,
                      const float* __restrict__ Res,
                      void* __restrict__ Cout,
                      int K, long strideB, long strideC, int epi)
{
    __shared__ __nv_bfloat16 As[2][BM * ASTRIDE];
    __shared__ __nv_bfloat16 Bs[2][BK * BSTRIDE];

    int tid = threadIdx.x;
    int m0 = blockIdx.y * BM;
    int p0 = blockIdx.x * BN;
    int b  = blockIdx.z;
    const __nv_bfloat16* Bp = Bact + (size_t)b * strideB;

    const __nv_bfloat16* Aptr0 = A + (size_t)(m0 + (tid >> 2)) * K + (tid & 3) * 8;
    const __nv_bfloat16* Aptr1 = A + (size_t)(m0 + 64 + (tid >> 2)) * K + (tid & 3) * 8;
    const __nv_bfloat16* Bptr0 = Bp + (size_t)(tid >> 4) * HW + p0 + (tid & 15) * 8;
    const __nv_bfloat16* Bptr1 = Bp + (size_t)(16 + (tid >> 4)) * HW + p0 + (tid & 15) * 8;

    unsigned int as_base = (unsigned int)__cvta_generic_to_shared(&As[0][0]);
    unsigned int bs_base = (unsigned int)__cvta_generic_to_shared(&Bs[0][0]);

    unsigned int sa0 = as_base + ((tid >> 2) * ASTRIDE + (tid & 3) * 8) * 2;
    unsigned int sa1 = as_base + ((64 + (tid >> 2)) * ASTRIDE + (tid & 3) * 8) * 2;
    unsigned int sb0 = bs_base + ((tid >> 4) * BSTRIDE + (tid & 15) * 8) * 2;
    unsigned int sb1 = bs_base + ((16 + (tid >> 4)) * BSTRIDE + (tid & 15) * 8) * 2;

    cp_async16(sa0, Aptr0);
    cp_async16(sa1, Aptr1);
    cp_async16(sb0, Bptr0);
    cp_async16(sb1, Bptr1);
    cp_commit();
    cp_wait0();
    __syncthreads();

    int warp = tid >> 5, lane = tid & 31;
    int wm = warp >> 2;
    int wn = warp & 3;

    float acc[4][4][4];
#pragma unroll
    for (int i = 0; i < 4; i++)
#pragma unroll
        for (int j = 0; j < 4; j++)
#pragma unroll
            for (int q = 0; q < 4; q++) acc[i][j][q] = 0.f;

    int a_row = wm * 64 + (lane & 15);
    int a_col = (lane >> 4) * 8;
    int b_row = (lane & 15);
    int b_col = wn * 32 + (lane >> 4) * 8;

    int nk = K >> 5;
    for (int kt = 0; kt < nk; kt++) {
        int buf = kt & 1;
        bool nxt = (kt + 1 < nk);
        if (nxt) {
            unsigned int ao = (buf ^ 1) * ASZ_BYTES;
            unsigned int bo = (buf ^ 1) * BSZ_BYTES;
            cp_async16(sa0 + ao, Aptr0 + (kt + 1) * BK);
            cp_async16(sa1 + ao, Aptr1 + (kt + 1) * BK);
            cp_async16(sb0 + bo, Bptr0 + (size_t)(kt + 1) * BK * HW);
            cp_async16(sb1 + bo, Bptr1 + (size_t)(kt + 1) * BK * HW);
            cp_commit();
        }

        unsigned int abase = as_base + buf * ASZ_BYTES;
        unsigned int bbase = bs_base + buf * BSZ_BYTES;
#pragma unroll
        for (int kk = 0; kk < 2; kk++) {
            unsigned int af[4][4];
            unsigned int bfr[2][4];
#pragma unroll
            for (int i = 0; i < 4; i++)
                ldsm_x4(af[i], abase + (((a_row + i * 16) * ASTRIDE) + a_col + kk * 16) * 2);
#pragma unroll
            for (int j = 0; j < 2; j++)
                ldsm_x4_t(bfr[j], bbase + (((b_row + kk * 16) * BSTRIDE) + b_col + j * 16) * 2);
#pragma unroll
            for (int i = 0; i < 4; i++)
#pragma unroll
                for (int jn = 0; jn < 4; jn++)
                    mma_bf16(acc[i][jn], af[i], &bfr[jn >> 1][(jn & 1) * 2]);
        }

        if (nxt) cp_wait0();
        __syncthreads();
    }

    int l4 = lane >> 2, l2 = (lane & 3) * 2;
#pragma unroll
    for (int i = 0; i < 4; i++) {
        int r0 = m0 + wm * 64 + i * 16 + l4;
        int r1 = r0 + 8;
        float bv0 = bias[r0], bv1 = bias[r1];
#pragma unroll
        for (int jn = 0; jn < 4; jn++) {
            int col = p0 + wn * 32 + jn * 8 + l2;
            size_t off0 = (size_t)b * strideC + (size_t)r0 * HW + col;
            size_t off1 = (size_t)b * strideC + (size_t)r1 * HW + col;
            float v0 = acc[i][jn][0] + bv0;
            float v1 = acc[i][jn][1] + bv0;
            float v2 = acc[i][jn][2] + bv1;
            float v3 = acc[i][jn][3] + bv1;
            if (epi == 1) {
                float* Cf = (float*)Cout;
                float2 q0 = *(const float2*)(Res + off0);
                float2 q1 = *(const float2*)(Res + off1);
                *(float2*)(Cf + off0) = make_float2(v0 + q0.x, v1 + q0.y);
                *(float2*)(Cf + off1) = make_float2(v2 + q1.x, v3 + q1.y);
            } else {
                if (epi == 2) {
                    v0 = gelu_f(v0); v1 = gelu_f(v1);
                    v2 = gelu_f(v2); v3 = gelu_f(v3);
                }
                __nv_bfloat16* Cb = (__nv_bfloat16*)Cout;
                *(unsigned int*)(Cb + off0) = pack_bf2(v0, v1);
                *(unsigned int*)(Cb + off1) = pack_bf2(v2, v3);
            }
        }
    }
}

// ---------------- tensor-core chunked attention ----------------
// One block (128 threads, 4 warps) per (b, g). qkv bf16 (b, s*256+c, p); chunk tokens p=g*64..+63.
// smem (bf16, row stride ATS=72):  QV [256][64] (Q then V), K [256][64] (K then O), P [64][64].
__global__ __launch_bounds__(128)
void attn_mma_kernel(const __nv_bfloat16* __restrict__ qkv, __nv_bfloat16* __restrict__ out)
{
    extern __shared__ __nv_bfloat16 ats[];
    __nv_bfloat16* QVs = ats + AT_QV;
    __nv_bfloat16* Ksm = ats + AT_K;
    __nv_bfloat16* Psm = ats + AT_P;

    unsigned int qv_base = (unsigned int)__cvta_generic_to_shared(QVs);
    unsigned int k_base  = (unsigned int)__cvta_generic_to_shared(Ksm);
    unsigned int p_base  = (unsigned int)__cvta_generic_to_shared(Psm);

    int g = blockIdx.x, b = blockIdx.y;
    int tid = threadIdx.x;
    int warp = tid >> 5, lane = tid & 31;
    const __nv_bfloat16* base = qkv + (size_t)b * 3 * CCH * HW + (size_t)g * CHUNK;

    // ---- load Q and K (each: 256 rows x 128B = 2048 x 16B) ----
#pragma unroll
    for (int k = 0; k < 16; k++) {
        int e = k * 128 + tid;           // 0..2047
        int c = e >> 3, seg = (e & 7) * 8;
        cp_async16(qv_base + (c * ATS + seg) * 2, base + (size_t)c * HW + seg);
        cp_async16(k_base  + (c * ATS + seg) * 2, base + (size_t)(256 + c) * HW + seg);
    }
    cp_commit();
    cp_wait0();
    __syncthreads();

    // ---- S = scale * Q^T K  (per warp: rows i0..i0+15, all 64 cols) ----
    int i0 = warp * 16;
    float acc[8][4];
#pragma unroll
    for (int t = 0; t < 8; t++)
#pragma unroll
        for (int q = 0; q < 4; q++) acc[t][q] = 0.f;

    // A (Q^T) via ldmatrix.trans from [c][i] storage
    int a_c = (lane & 7) + ((lane >> 4) << 3);   // +kk*16
    int a_m = i0 + ((lane >> 3) & 1) * 8;
    // B (K) via ldmatrix.trans from [c][j] storage (verified GEMM pattern)
    int b_c = (lane & 15);                       // +kk*16
    int b_j = (lane >> 4) * 8;                   // +jt*16

#pragma unroll
    for (int kk = 0; kk < 16; kk++) {
        unsigned int af[4];
        ldsm_x4_t(af, qv_base + (((kk * 16 + a_c) * ATS) + a_m) * 2);
#pragma unroll
        for (int jt = 0; jt < 4; jt++) {
            unsigned int bfr[4];
            ldsm_x4_t(bfr, k_base + (((kk * 16 + b_c) * ATS) + jt * 16 + b_j) * 2);
            mma_bf16(acc[jt * 2 + 0], af, &bfr[0]);
            mma_bf16(acc[jt * 2 + 1], af, &bfr[2]);
        }
    }

    // ---- softmax (rows r = i0 + lane/4 and r+8; cols jc = t*8 + (lane%4)*2 +{0,1}) ----
    {
        const float SC = 0.0625f;
#pragma unroll
        for (int t = 0; t < 8; t++)
#pragma unroll
            for (int q = 0; q < 4; q++) acc[t][q] *= SC;

        float mxA = -1e30f, mxB = -1e30f;
#pragma unroll
        for (int t = 0; t < 8; t++) {
            mxA = fmaxf(mxA, fmaxf(acc[t][0], acc[t][1]));
            mxB = fmaxf(mxB, fmaxf(acc[t][2], acc[t][3]));
        }
        mxA = fmaxf(mxA, __shfl_xor_sync(0xffffffffu, mxA, 1));
        mxA = fmaxf(mxA, __shfl_xor_sync(0xffffffffu, mxA, 2));
        mxB = fmaxf(mxB, __shfl_xor_sync(0xffffffffu, mxB, 1));
        mxB = fmaxf(mxB, __shfl_xor_sync(0xffffffffu, mxB, 2));

        float sA = 0.f, sB = 0.f;
#pragma unroll
        for (int t = 0; t < 8; t++) {
            acc[t][0] = expf(acc[t][0] - mxA); sA += acc[t][0];
            acc[t][1] = expf(acc[t][1] - mxA); sA += acc[t][1];
            acc[t][2] = expf(acc[t][2] - mxB); sB += acc[t][2];
            acc[t][3] = expf(acc[t][3] - mxB); sB += acc[t][3];
        }
        sA += __shfl_xor_sync(0xffffffffu, sA, 1);
        sA += __shfl_xor_sync(0xffffffffu, sA, 2);
        sB += __shfl_xor_sync(0xffffffffu, sB, 1);
        sB += __shfl_xor_sync(0xffffffffu, sB, 2);
        float iA = 1.0f / sA, iB = 1.0f / sB;
#pragma unroll
        for (int t = 0; t < 8; t++) {
            acc[t][0] *= iA; acc[t][1] *= iA;
            acc[t][2] *= iB; acc[t][3] *= iB;
        }
    }

    __syncthreads();   // all warps done reading Q (QVs) and K

    // ---- store P [i][j] bf16; start V load into QVs ----
#pragma unroll
    for (int k = 0; k < 16; k++) {
        int e = k * 128 + tid;
        int c = e >> 3, seg = (e & 7) * 8;
        cp_async16(qv_base + (c * ATS + seg) * 2, base + (size_t)(512 + c) * HW + seg);
    }
    cp_commit();
    {
        int r = i0 + (lane >> 2);
#pragma unroll
        for (int t = 0; t < 8; t++) {
            int jc = t * 8 + (lane & 3) * 2;
            *(unsigned int*)(Psm + r * ATS + jc)       = pack_bf2(acc[t][0], acc[t][1]);
            *(unsigned int*)(Psm + (r + 8) * ATS + jc) = pack_bf2(acc[t][2], acc[t][3]);
        }
    }
    cp_wait0();
    __syncthreads();   // V in QVs, P complete

    // ---- O^T = P @ V^T : m=i(64), n=c(256), k=j(64). warp covers c0 = warp*64, 2 passes of n32 ----
    // A = P [i][j] row-major: GEMM-A non-trans pattern
    int ap_r = (lane & 15);              // + it*16
    int ap_k = (lane >> 4) * 8;          // + kk*16
    // B = V stored [c][j] = [n][k]: non-trans, mats (n0-7,k0-7),(n0-7,k8-15),(n8-15,k0-7),(n8-15,k8-15)
    int bv_n = (lane & 7) + ((lane >> 4) << 3);   // + cbase + nt*16
    int bv_k = ((lane >> 3) & 1) * 8;             // + kk*16

#pragma unroll
    for (int pass = 0; pass < 2; pass++) {
        int cbase = warp * 64 + pass * 32;
        float oc[4][4][4];
#pragma unroll
        for (int it = 0; it < 4; it++)
#pragma unroll
            for (int nn = 0; nn < 4; nn++)
#pragma unroll
                for (int q = 0; q < 4; q++) oc[it][nn][q] = 0.f;

#pragma unroll
        for (int kk = 0; kk < 4; kk++) {
            unsigned int ap[4][4];
#pragma unroll
            for (int it = 0; it < 4; it++)
                ldsm_x4(ap[it], p_base + (((it * 16 + ap_r) * ATS) + kk * 16 + ap_k) * 2);
            unsigned int bv[2][4];
#pragma unroll
            for (int nt = 0; nt < 2; nt++)
                ldsm_x4(bv[nt], qv_base + (((cbase + nt * 16 + bv_n) * ATS) + kk * 16 + bv_k) * 2);
#pragma unroll
            for (int it = 0; it < 4; it++)
#pragma unroll
                for (int nn = 0; nn < 4; nn++)
                    mma_bf16(oc[it][nn], ap[it], &bv[nn >> 1][(nn & 1) * 2]);
        }

        // write O^T[i][c] -> Osm[c][i] (Osm = K buffer, free after S-phase)
#pragma unroll
        for (int it = 0; it < 4; it++) {
            int r = it * 16 + (lane >> 2);
#pragma unroll
            for (int nn = 0; nn < 4; nn++) {
                int cc = cbase + nn * 8 + (lane & 3) * 2;
                Ksm[cc * ATS + r]           = __float2bfloat16(oc[it][nn][0]);
                Ksm[(cc + 1) * ATS + r]     = __float2bfloat16(oc[it][nn][1]);
                Ksm[cc * ATS + r + 8]       = __float2bfloat16(oc[it][nn][2]);
                Ksm[(cc + 1) * ATS + r + 8] = __float2bfloat16(oc[it][nn][3]);
            }
        }
    }
    __syncthreads();

    // ---- coalesced copy Osm -> out ----
    __nv_bfloat16* op = out + (size_t)b * CCH * HW + (size_t)g * CHUNK;
#pragma unroll
    for (int k = 0; k < 16; k++) {
        int e = k * 128 + tid;
        int c = e >> 3, seg = (e & 7) * 8;
        *(uint4*)(op + (size_t)c * HW + seg) = *(uint4*)(Ksm + c * ATS + seg);
    }
}

// ---------------- depthwise 3x3 conv + bias + gelu (bf16 in/out) ----------------
__global__ void dwconv_kernel(const __nv_bfloat16* __restrict__ in,
                              const float* __restrict__ w,
                              const float* __restrict__ bias,
                              __nv_bfloat16* __restrict__ out)
{
    int idx = blockIdx.x * 256 + threadIdx.x;
    int x = idx & 127;
    int y = (idx >> 7) & 127;
    int c = (idx >> 14) & (HID - 1);
    const __nv_bfloat16* ip = in + ((size_t)(idx >> 14) << 14);
    const float* wp = w + c * 9;

    float acc = 0.f;
#pragma unroll
    for (int ky = 0; ky < 3; ky++) {
        int yy = y + ky - 1;
        if (yy < 0 || yy > 127) continue;
#pragma unroll
        for (int kx = 0; kx < 3; kx++) {
            int xx = x + kx - 1;
            if (xx < 0 || xx > 127) continue;
            acc += __bfloat162float(ip[yy * 128 + xx]) * wp[ky * 3 + kx];
        }
    }
    acc += bias[c];
    out[idx] = __float2bfloat16(gelu_f(acc));
}

// ---------------- launcher ----------------
extern "C" void kernel_launch(void* const* d_in, const int* in_sizes, int n_in,
                              void* d_out, int out_size)
{
    const float* x       = (const float*)d_in[0];
    const float* ln1_s   = (const float*)d_in[1];
    const float* ln1_b   = (const float*)d_in[2];
    const float* qkv_w   = (const float*)d_in[3];
    const float* qkv_b   = (const float*)d_in[4];
    const float* proj_w  = (const float*)d_in[5];
    const float* proj_b  = (const float*)d_in[6];
    const float* ln2_s   = (const float*)d_in[7];
    const float* ln2_b   = (const float*)d_in[8];
    const float* conv1_w = (const float*)d_in[9];
    const float* conv1_b = (const float*)d_in[10];
    const float* conv2_w = (const float*)d_in[11];
    const float* conv2_b = (const float*)d_in[12];
    const float* conv3_w = (const float*)d_in[13];
    const float* conv3_b = (const float*)d_in[14];
    float* outp = (float*)d_out;

    __nv_bfloat16 *xln, *qkv, *attnp, *h1, *h2, *wbf;
    float *x2;
    cudaGetSymbolAddress((void**)&xln,   g_xln);
    cudaGetSymbolAddress((void**)&qkv,   g_qkv);
    cudaGetSymbolAddress((void**)&attnp, g_attn);
    cudaGetSymbolAddress((void**)&x2,    g_x2);
    cudaGetSymbolAddress((void**)&h1,    g_h1);
    cudaGetSymbolAddress((void**)&h2,    g_h2);
    cudaGetSymbolAddress((void**)&wbf,   g_wbf);

    __nv_bfloat16* w_qkv = wbf;
    __nv_bfloat16* w_prj = w_qkv + 768 * 256;
    __nv_bfloat16* w_c1  = w_prj + 256 * 256;
    __nv_bfloat16* w_c3  = w_c1 + 512 * 256;

    cudaFuncSetAttribute(attn_mma_kernel, cudaFuncAttributeMaxDynamicSharedMemorySize, AT_SMEM_BYTES);
    cudaFuncSetAttribute(ln_kernel, cudaFuncAttributeMaxDynamicSharedMemorySize, LN_SMEM_BYTES);

    // 0) weight conversion (one launch)
    cvt_all_kernel<<<524288 / 256, 256>>>(qkv_w, proj_w, conv1_w, conv3_w, wbf);

    // 1) LN1
    ln_kernel<<<BATCH * 256, 256, LN_SMEM_BYTES>>>(x, ln1_s, ln1_b, xln);

    // 2) QKV GEMM -> qkv bf16
    gemm_bf16_kernel<<<dim3(HW / BN, 768 / BM, BATCH), 256>>>(
        w_qkv, xln, qkv_b, nullptr, qkv, 256,
        (long)CCH * HW, (long)3 * CCH * HW, 0);

    // 3) tensor-core chunked attention -> attn bf16
    attn_mma_kernel<<<dim3(NG, BATCH), 128, AT_SMEM_BYTES>>>(qkv, attnp);

    // 4) proj GEMM + residual(x) -> x2 fp32
    gemm_bf16_kernel<<<dim3(HW / BN, 256 / BM, BATCH), 256>>>(
        w_prj, attnp, proj_b, x, x2, 256,
        (long)CCH * HW, (long)CCH * HW, 1);

    // 5) LN2
    ln_kernel<<<BATCH * 256, 256, LN_SMEM_BYTES>>>(x2, ln2_s, ln2_b, xln);

    // 6) conv1 (1x1) + gelu -> h1 bf16
    gemm_bf16_kernel<<<dim3(HW / BN, 512 / BM, BATCH), 256>>>(
        w_c1, xln, conv1_b, nullptr, h1, 256,
        (long)CCH * HW, (long)HID * HW, 2);

    // 7) depthwise 3x3 + gelu -> h2 bf16
    dwconv_kernel<<<BATCH * HID * HW / 256, 256>>>(h1, conv2_w, conv2_b, h2);

    // 8) conv3 (1x1) + residual(x2) -> out fp32
    gemm_bf16_kernel<<<dim3(HW / BN, 256 / BM, BATCH), 256>>>(
        w_c3, h2, conv3_b, x2, outp, 512,
        (long)HID * HW, (long)CCH * HW, 1);
}